// round 9
// baseline (speedup 1.0000x reference)
#include <cuda_runtime.h>
#include <cuda_bf16.h>
#include <cstdint>

#define B_  4
#define S_  2048
#define D_  1024
#define H_  16
#define DK_ 10
#define DV_ 12
#define HK  (H_*DV_)      // 192
#define PAD 16            // padded row width for q scratch
#define KST 20            // g_k row stride (10 dims duplicated)
#define VST 24            // g_v row stride (12 dims duplicated)
#define NW  192           // packed N per section

typedef unsigned long long ull;

// ---------------- scratch (device globals; no allocation allowed) ----------
__device__ __nv_bfloat16 g_wbh[3*D_*NW];   // [sec][d][n] bf16 hi
__device__ __nv_bfloat16 g_wbl[3*D_*NW];   // [sec][d][n] bf16 lo
__device__ float g_q[B_*H_*S_*PAD];        // [bh][s][16] (10 valid)
__device__ float g_k[B_*H_*S_*KST];        // [bh][s][20] dup pairs (k_d,k_d)
__device__ float g_v[B_*H_*S_*VST];        // [bh][s][24] dup pairs (v_d,v_d)
__device__ float g_heads[B_*S_*HK];        // [b*s][192]

// ---------------- packed f32x2 helpers ------------------------------------
__device__ __forceinline__ ull pk2(float lo, float hi) {
    ull r; asm("mov.b64 %0, {%1,%2};" : "=l"(r) : "f"(lo), "f"(hi)); return r;
}
__device__ __forceinline__ ull fma2(ull a, ull b, ull c) {
    ull d; asm("fma.rn.f32x2 %0, %1, %2, %3;" : "=l"(d) : "l"(a), "l"(b), "l"(c)); return d;
}
__device__ __forceinline__ ull mul2(ull a, ull b) {
    ull d; asm("mul.rn.f32x2 %0, %1, %2;" : "=l"(d) : "l"(a), "l"(b)); return d;
}
__device__ __forceinline__ float2 upk2(ull v) {
    float2 r; asm("mov.b64 {%0,%1}, %2;" : "=f"(r.x), "=f"(r.y) : "l"(v)); return r;
}
__device__ __forceinline__ float ex2(float x) {
    float r; asm("ex2.approx.f32 %0, %1;" : "=f"(r) : "f"(x)); return r;
}

// ---------------- legacy tensor helpers (baseline PTX, sm_80-era) ---------
__device__ __forceinline__ uint32_t smem_u32(const void* p) {
    uint32_t a;
    asm("{ .reg .u64 t; cvta.to.shared.u64 t, %1; cvt.u32.u64 %0, t; }" : "=r"(a) : "l"(p));
    return a;
}
__device__ __forceinline__ void ldmx4(uint32_t* r, uint32_t a) {
    asm volatile("ldmatrix.sync.aligned.m8n8.x4.shared.b16 {%0,%1,%2,%3}, [%4];"
                 : "=r"(r[0]), "=r"(r[1]), "=r"(r[2]), "=r"(r[3]) : "r"(a));
}
__device__ __forceinline__ void ldmx4t(uint32_t* r, uint32_t a) {
    asm volatile("ldmatrix.sync.aligned.m8n8.x4.trans.shared.b16 {%0,%1,%2,%3}, [%4];"
                 : "=r"(r[0]), "=r"(r[1]), "=r"(r[2]), "=r"(r[3]) : "r"(a));
}
__device__ __forceinline__ void mma16816(float* c, const uint32_t* a,
                                         uint32_t b0, uint32_t b1) {
    asm volatile(
        "mma.sync.aligned.m16n8k16.row.col.f32.bf16.bf16.f32 "
        "{%0,%1,%2,%3}, {%4,%5,%6,%7}, {%8,%9}, {%0,%1,%2,%3};"
        : "+f"(c[0]), "+f"(c[1]), "+f"(c[2]), "+f"(c[3])
        : "r"(a[0]), "r"(a[1]), "r"(a[2]), "r"(a[3]), "r"(b0), "r"(b1));
}
__device__ __forceinline__ uint32_t bf2u(__nv_bfloat162 v) {
    return *reinterpret_cast<uint32_t*>(&v);
}

// ==========================================================================
// Kernel 0: pack W -> bf16 hi/lo, [sec][d][n] with n = h*12 + j (zero-pad).
// ==========================================================================
__global__ void pack_w_kernel(const float* __restrict__ WQ,
                              const float* __restrict__ WK,
                              const float* __restrict__ WV)
{
    int idx = blockIdx.x * 256 + threadIdx.x;   // 0 .. 3*1024*192-1
    int sec = idx / (D_ * NW);
    int rem = idx - sec * (D_ * NW);
    int d   = rem / NW;
    int n   = rem - d * NW;
    int h   = n / 12, j = n - h * 12;
    float v = 0.f;
    if (sec == 0)      { if (j < DK_) v = WQ[(h * D_ + d) * DK_ + j]; }
    else if (sec == 1) { if (j < DK_) v = WK[(h * D_ + d) * DK_ + j]; }
    else               {              v = WV[(h * D_ + d) * DV_ + j]; }
    __nv_bfloat16 hi = __float2bfloat16(v);
    __nv_bfloat16 lo = __float2bfloat16(v - __bfloat162float(hi));
    g_wbh[idx] = hi;
    g_wbl[idx] = lo;
}

// ==========================================================================
// Kernel 1: projection GEMM on legacy tensor cores (mma.sync bf16, 2-word
// split: ah*bh + ah*bl + al*bh). C tile 64x192 per CTA, BK=32, 4 warps.
// Epilogue scatters Q to [bh][s][16], K/V to DUPLICATED-pair layouts that
// the query-packed attention consumes directly.
// ==========================================================================
__global__ void __launch_bounds__(128, 3)
proj_mma_kernel(const float* __restrict__ Qi,
                const float* __restrict__ Ki,
                const float* __restrict__ Vi)
{
    const int z  = blockIdx.y;
    const float* A = (z == 0) ? Qi : (z == 1) ? Ki : Vi;
    const int m0 = blockIdx.x * 64;
    const int tid  = threadIdx.x;     // 128
    const int w    = tid >> 5;
    const int lane = tid & 31;

    __shared__ __align__(16) __nv_bfloat16 Ah[64][40];   // 80B stride
    __shared__ __align__(16) __nv_bfloat16 Al[64][40];
    __shared__ __align__(16) __nv_bfloat16 Bh[32][200];  // 400B stride
    __shared__ __align__(16) __nv_bfloat16 Bl[32][200];

    const uint32_t AhB = smem_u32(&Ah[0][0]);
    const uint32_t AlB = smem_u32(&Al[0][0]);
    const uint32_t BhB = smem_u32(&Bh[0][0]);
    const uint32_t BlB = smem_u32(&Bl[0][0]);

    float acc[24][4];
    #pragma unroll
    for (int t = 0; t < 24; t++)
        #pragma unroll
        for (int u = 0; u < 4; u++) acc[t][u] = 0.f;

    const __nv_bfloat16* wbh = g_wbh + (size_t)z * D_ * NW;
    const __nv_bfloat16* wbl = g_wbl + (size_t)z * D_ * NW;

    for (int k0 = 0; k0 < D_; k0 += 32) {
        // ---- stage A: 64x32 f32 -> bf16 hi/lo. 512 float4, 4/thread ----
        #pragma unroll
        for (int l = 0; l < 4; l++) {
            int f   = tid + l * 128;
            int row = f >> 3, c4 = f & 7;
            float4 a = *(const float4*)(A + (size_t)(m0 + row) * D_ + k0 + c4 * 4);
            __nv_bfloat16 hx = __float2bfloat16(a.x), hy = __float2bfloat16(a.y);
            __nv_bfloat16 hz = __float2bfloat16(a.z), hw = __float2bfloat16(a.w);
            __nv_bfloat16 lx = __float2bfloat16(a.x - __bfloat162float(hx));
            __nv_bfloat16 ly = __float2bfloat16(a.y - __bfloat162float(hy));
            __nv_bfloat16 lz = __float2bfloat16(a.z - __bfloat162float(hz));
            __nv_bfloat16 lw = __float2bfloat16(a.w - __bfloat162float(hw));
            *(uint32_t*)&Ah[row][c4 * 4 + 0] = bf2u(__nv_bfloat162(hx, hy));
            *(uint32_t*)&Ah[row][c4 * 4 + 2] = bf2u(__nv_bfloat162(hz, hw));
            *(uint32_t*)&Al[row][c4 * 4 + 0] = bf2u(__nv_bfloat162(lx, ly));
            *(uint32_t*)&Al[row][c4 * 4 + 2] = bf2u(__nv_bfloat162(lz, lw));
        }
        // ---- stage B: 32x192 bf16 hi/lo, uint4 copies, 6+6 per thread ----
        #pragma unroll
        for (int l = 0; l < 6; l++) {
            int idx = tid + l * 128;        // 0..767
            int kk  = idx / 24;
            int u   = idx - kk * 24;
            *(uint4*)&Bh[kk][u * 8] = *(const uint4*)(wbh + (size_t)(k0 + kk) * NW + u * 8);
            *(uint4*)&Bl[kk][u * 8] = *(const uint4*)(wbl + (size_t)(k0 + kk) * NW + u * 8);
        }
        __syncthreads();

        #pragma unroll
        for (int ks = 0; ks < 2; ks++) {
            uint32_t aoff = (uint32_t)(w * 16 + (lane & 15)) * 80
                          + (uint32_t)(ks * 16 + (lane >> 4) * 8) * 2;
            uint32_t ah[4], al[4];
            ldmx4(ah, AhB + aoff);
            ldmx4(al, AlB + aoff);

            uint32_t brow = (uint32_t)(ks * 16 + ((lane >> 3) & 1) * 8 + (lane & 7));
            uint32_t bbase = brow * 400 + (uint32_t)(lane >> 4) * 16;

            #pragma unroll
            for (int nt = 0; nt < 12; nt++) {
                uint32_t bh[4], bl[4];
                ldmx4t(bh, BhB + bbase + nt * 32);
                ldmx4t(bl, BlB + bbase + nt * 32);
                mma16816(acc[nt * 2 + 0], ah, bh[0], bh[1]);
                mma16816(acc[nt * 2 + 0], al, bh[0], bh[1]);
                mma16816(acc[nt * 2 + 0], ah, bl[0], bl[1]);
                mma16816(acc[nt * 2 + 1], ah, bh[2], bh[3]);
                mma16816(acc[nt * 2 + 1], al, bh[2], bh[3]);
                mma16816(acc[nt * 2 + 1], ah, bl[2], bl[3]);
            }
        }
        __syncthreads();
    }

    // ---- epilogue: frag (c0,c1)@row r, (c2,c3)@row r+8; scatter ----
    const int b  = m0 >> 11;
    const int s0 = (m0 & 2047) + w * 16 + (lane >> 2);
    const int lc = lane & 3;
    #pragma unroll
    for (int t = 0; t < 24; t++) {
        int n = t * 8 + lc * 2;          // even -> (n, n+1) same head
        int h = n / 12, j = n - h * 12;
        int bh = b * H_ + h;
        if (z == 0) {
            float* o = g_q + ((size_t)bh * S_ + s0) * PAD + j;
            *(float2*)o             = make_float2(acc[t][0], acc[t][1]);
            *(float2*)(o + 8 * PAD) = make_float2(acc[t][2], acc[t][3]);
        } else if (z == 1) {
            if (j < DK_) {
                float* o = g_k + ((size_t)bh * S_ + s0) * KST + 2 * j;
                *(float4*)o             = make_float4(acc[t][0], acc[t][0], acc[t][1], acc[t][1]);
                *(float4*)(o + 8 * KST) = make_float4(acc[t][2], acc[t][2], acc[t][3], acc[t][3]);
            }
        } else {
            float* o = g_v + ((size_t)bh * S_ + s0) * VST + 2 * j;
            *(float4*)o             = make_float4(acc[t][0], acc[t][0], acc[t][1], acc[t][1]);
            *(float4*)(o + 8 * VST) = make_float4(acc[t][2], acc[t][2], acc[t][3], acc[t][3]);
        }
    }
}

// ==========================================================================
// Kernel 2: query-packed streaming attention, max-free single-pass softmax.
// 128 threads, 4 queries/thread as 2 f32x2 pairs: lanes carry (qa,qb).
// K/V tiles are pre-duplicated (k_d,k_d): scores accumulate (s_a,s_b)
// jointly with NO h-sum; denom rides as a 13th accumulator against a
// ones-column in the V tile. grid (64 bh, 4 q-tiles of 512).
// ==========================================================================
__global__ void __launch_bounds__(128, 3) attn_kernel()
{
    const int bh  = blockIdx.x;
    const int b   = bh >> 4;
    const int h   = bh & 15;
    const int q0  = blockIdx.y * 512;
    const int tid = threadIdx.x;

    const float scale2 = 0.45622024f;   // (1/sqrt(10)) * log2(e)

    __shared__ __align__(16) float Ks[128][KST];   // 80B rows
    __shared__ __align__(16) float Vs[128][28];    // 112B rows (24 data + ones)

    // queries: a=q0+tid, b=+128 (pair0); c=+256, d=+384 (pair1)
    ull p0[10], p1[10];
    {
        const float* qa = g_q + ((size_t)bh * S_ + q0 + tid) * PAD;
        const float* qb = qa + (size_t)128 * PAD;
        const float* qc = qa + (size_t)256 * PAD;
        const float* qd = qa + (size_t)384 * PAD;
        #pragma unroll
        for (int d = 0; d < 10; d++) {
            p0[d] = pk2(qa[d] * scale2, qb[d] * scale2);
            p1[d] = pk2(qc[d] * scale2, qd[d] * scale2);
        }
    }

    ull acc0[13], acc1[13];
    #pragma unroll
    for (int d = 0; d < 13; d++) { acc0[d] = 0ULL; acc1[d] = 0ULL; }

    const float* kg = g_k + (size_t)bh * S_ * KST;
    const float* vg = g_v + (size_t)bh * S_ * VST;

    for (int t0 = 0; t0 < S_; t0 += 128) {
        __syncthreads();
        #pragma unroll
        for (int l = 0; l < 5; l++) {
            int idx = tid + l * 128;          // 640 f4: 5 per key row
            int row = idx / 5, c = idx - row * 5;
            *(float4*)&Ks[row][c * 4] =
                *(const float4*)(kg + (size_t)(t0 + row) * KST + c * 4);
        }
        #pragma unroll
        for (int l = 0; l < 6; l++) {
            int idx = tid + l * 128;          // 768 f4: 6 per key row
            int row = idx / 6, c = idx - row * 6;
            *(float4*)&Vs[row][c * 4] =
                *(const float4*)(vg + (size_t)(t0 + row) * VST + c * 4);
        }
        *(float4*)&Vs[tid][24] = make_float4(1.f, 1.f, 1.f, 1.f);
        __syncthreads();

        #pragma unroll 2
        for (int j = 0; j < 128; j++) {
            ulonglong2 k01 = *(const ulonglong2*)&Ks[j][0];
            ulonglong2 k23 = *(const ulonglong2*)&Ks[j][4];
            ulonglong2 k45 = *(const ulonglong2*)&Ks[j][8];
            ulonglong2 k67 = *(const ulonglong2*)&Ks[j][12];
            ulonglong2 k89 = *(const ulonglong2*)&Ks[j][16];

            ull s0 = mul2(p0[0], k01.x);
            ull s1 = mul2(p1[0], k01.x);
            s0 = fma2(p0[1], k01.y, s0);  s1 = fma2(p1[1], k01.y, s1);
            s0 = fma2(p0[2], k23.x, s0);  s1 = fma2(p1[2], k23.x, s1);
            s0 = fma2(p0[3], k23.y, s0);  s1 = fma2(p1[3], k23.y, s1);
            s0 = fma2(p0[4], k45.x, s0);  s1 = fma2(p1[4], k45.x, s1);
            s0 = fma2(p0[5], k45.y, s0);  s1 = fma2(p1[5], k45.y, s1);
            s0 = fma2(p0[6], k67.x, s0);  s1 = fma2(p1[6], k67.x, s1);
            s0 = fma2(p0[7], k67.y, s0);  s1 = fma2(p1[7], k67.y, s1);
            s0 = fma2(p0[8], k89.x, s0);  s1 = fma2(p1[8], k89.x, s1);
            s0 = fma2(p0[9], k89.y, s0);  s1 = fma2(p1[9], k89.y, s1);

            float2 f0 = upk2(s0), f1 = upk2(s1);
            ull P0 = pk2(ex2(f0.x), ex2(f0.y));   // (p_a, p_b)
            ull P1 = pk2(ex2(f1.x), ex2(f1.y));   // (p_c, p_d)

            ulonglong2 v01 = *(const ulonglong2*)&Vs[j][0];
            ulonglong2 v23 = *(const ulonglong2*)&Vs[j][4];
            ulonglong2 v45 = *(const ulonglong2*)&Vs[j][8];
            ulonglong2 v67 = *(const ulonglong2*)&Vs[j][12];
            ulonglong2 v89 = *(const ulonglong2*)&Vs[j][16];
            ulonglong2 vab = *(const ulonglong2*)&Vs[j][20];
            ull vden = *(const ull*)&Vs[j][24];   // (1,1)

            acc0[0]  = fma2(P0, v01.x, acc0[0]);   acc1[0]  = fma2(P1, v01.x, acc1[0]);
            acc0[1]  = fma2(P0, v01.y, acc0[1]);   acc1[1]  = fma2(P1, v01.y, acc1[1]);
            acc0[2]  = fma2(P0, v23.x, acc0[2]);   acc1[2]  = fma2(P1, v23.x, acc1[2]);
            acc0[3]  = fma2(P0, v23.y, acc0[3]);   acc1[3]  = fma2(P1, v23.y, acc1[3]);
            acc0[4]  = fma2(P0, v45.x, acc0[4]);   acc1[4]  = fma2(P1, v45.x, acc1[4]);
            acc0[5]  = fma2(P0, v45.y, acc0[5]);   acc1[5]  = fma2(P1, v45.y, acc1[5]);
            acc0[6]  = fma2(P0, v67.x, acc0[6]);   acc1[6]  = fma2(P1, v67.x, acc1[6]);
            acc0[7]  = fma2(P0, v67.y, acc0[7]);   acc1[7]  = fma2(P1, v67.y, acc1[7]);
            acc0[8]  = fma2(P0, v89.x, acc0[8]);   acc1[8]  = fma2(P1, v89.x, acc1[8]);
            acc0[9]  = fma2(P0, v89.y, acc0[9]);   acc1[9]  = fma2(P1, v89.y, acc1[9]);
            acc0[10] = fma2(P0, vab.x, acc0[10]);  acc1[10] = fma2(P1, vab.x, acc1[10]);
            acc0[11] = fma2(P0, vab.y, acc0[11]);  acc1[11] = fma2(P1, vab.y, acc1[11]);
            acc0[12] = fma2(P0, vden,  acc0[12]);  acc1[12] = fma2(P1, vden,  acc1[12]);
        }
    }

    // epilogue: acc[d] = (out for query lo, out for query hi); denom at [12]
    float* oa = g_heads + (size_t)(b * S_ + q0 + tid) * HK + h * DV_;
    {
        float2 den = upk2(acc0[12]);
        float ia = 1.f / den.x, ib = 1.f / den.y;
        float2 r[12];
        #pragma unroll
        for (int d = 0; d < 12; d++) r[d] = upk2(acc0[d]);
        float* ob = oa + (size_t)128 * HK;
        *(float4*)(oa + 0) = make_float4(r[0].x * ia, r[1].x * ia, r[2].x * ia, r[3].x * ia);
        *(float4*)(oa + 4) = make_float4(r[4].x * ia, r[5].x * ia, r[6].x * ia, r[7].x * ia);
        *(float4*)(oa + 8) = make_float4(r[8].x * ia, r[9].x * ia, r[10].x * ia, r[11].x * ia);
        *(float4*)(ob + 0) = make_float4(r[0].y * ib, r[1].y * ib, r[2].y * ib, r[3].y * ib);
        *(float4*)(ob + 4) = make_float4(r[4].y * ib, r[5].y * ib, r[6].y * ib, r[7].y * ib);
        *(float4*)(ob + 8) = make_float4(r[8].y * ib, r[9].y * ib, r[10].y * ib, r[11].y * ib);
    }
    {
        float2 den = upk2(acc1[12]);
        float ic = 1.f / den.x, id = 1.f / den.y;
        float2 r[12];
        #pragma unroll
        for (int d = 0; d < 12; d++) r[d] = upk2(acc1[d]);
        float* oc = oa + (size_t)256 * HK;
        float* od = oa + (size_t)384 * HK;
        *(float4*)(oc + 0) = make_float4(r[0].x * ic, r[1].x * ic, r[2].x * ic, r[3].x * ic);
        *(float4*)(oc + 4) = make_float4(r[4].x * ic, r[5].x * ic, r[6].x * ic, r[7].x * ic);
        *(float4*)(oc + 8) = make_float4(r[8].x * ic, r[9].x * ic, r[10].x * ic, r[11].x * ic);
        *(float4*)(od + 0) = make_float4(r[0].y * id, r[1].y * id, r[2].y * id, r[3].y * id);
        *(float4*)(od + 4) = make_float4(r[4].y * id, r[5].y * id, r[6].y * id, r[7].y * id);
        *(float4*)(od + 8) = make_float4(r[8].y * id, r[9].y * id, r[10].y * id, r[11].y * id);
    }
}

// ==========================================================================
// Kernel 3: out[8192,1024] = heads[8192,192] @ WO[192,1024] (unchanged).
// ==========================================================================
__global__ void __launch_bounds__(256, 4)
outproj_kernel(const float* __restrict__ WO,
               float* __restrict__ out)
{
    const int m0 = blockIdx.x * 64;
    const int n0 = blockIdx.y * 128;

    __shared__ __align__(16) float As[32][68];
    __shared__ __align__(16) float Bs[32][128];

    const int tid = threadIdx.x;   // 256
    const int tr  = tid & 15;
    const int tc  = tid >> 4;

    ull acc[4][4];
    #pragma unroll
    for (int i = 0; i < 4; i++)
        #pragma unroll
        for (int u = 0; u < 4; u++) acc[i][u] = 0ULL;

    for (int k0 = 0; k0 < HK; k0 += 32) {
        #pragma unroll
        for (int l = 0; l < 2; l++) {
            int idx = tid + l * 256;
            int row = idx >> 3, c4 = idx & 7;
            float4 a = *(const float4*)(g_heads + (size_t)(m0 + row) * HK + k0 + c4 * 4);
            As[c4 * 4 + 0][row] = a.x;
            As[c4 * 4 + 1][row] = a.y;
            As[c4 * 4 + 2][row] = a.z;
            As[c4 * 4 + 3][row] = a.w;
        }
        #pragma unroll
        for (int l = 0; l < 4; l++) {
            int idx = tid + l * 256;
            int kk  = idx >> 5;
            int c4  = idx & 31;
            float4 w = *(const float4*)(WO + (size_t)(k0 + kk) * D_ + n0 + c4 * 4);
            *(float4*)&Bs[kk][c4 * 4] = w;
        }
        __syncthreads();

        #pragma unroll 16
        for (int k = 0; k < 32; k++) {
            float4 av = *(const float4*)&As[k][tr * 4];
            ull a0 = pk2(av.x, av.x), a1 = pk2(av.y, av.y);
            ull a2 = pk2(av.z, av.z), a3 = pk2(av.w, av.w);
            const ulonglong2* bp = (const ulonglong2*)&Bs[k][tc * 8];
            ulonglong2 b01 = bp[0], b23 = bp[1];
            acc[0][0] = fma2(a0, b01.x, acc[0][0]);
            acc[0][1] = fma2(a0, b01.y, acc[0][1]);
            acc[0][2] = fma2(a0, b23.x, acc[0][2]);
            acc[0][3] = fma2(a0, b23.y, acc[0][3]);
            acc[1][0] = fma2(a1, b01.x, acc[1][0]);
            acc[1][1] = fma2(a1, b01.y, acc[1][1]);
            acc[1][2] = fma2(a1, b23.x, acc[1][2]);
            acc[1][3] = fma2(a1, b23.y, acc[1][3]);
            acc[2][0] = fma2(a2, b01.x, acc[2][0]);
            acc[2][1] = fma2(a2, b01.y, acc[2][1]);
            acc[2][2] = fma2(a2, b23.x, acc[2][2]);
            acc[2][3] = fma2(a2, b23.y, acc[2][3]);
            acc[3][0] = fma2(a3, b01.x, acc[3][0]);
            acc[3][1] = fma2(a3, b01.y, acc[3][1]);
            acc[3][2] = fma2(a3, b23.x, acc[3][2]);
            acc[3][3] = fma2(a3, b23.y, acc[3][3]);
        }
        __syncthreads();
    }

    #pragma unroll
    for (int i = 0; i < 4; i++) {
        float* o = out + (size_t)(m0 + tr * 4 + i) * D_ + n0 + tc * 8;
        float2 c0 = upk2(acc[i][0]), c1 = upk2(acc[i][1]);
        float2 c2 = upk2(acc[i][2]), c3 = upk2(acc[i][3]);
        *(float4*)(o + 0) = make_float4(c0.x, c0.y, c1.x, c1.y);
        *(float4*)(o + 4) = make_float4(c2.x, c2.y, c3.x, c3.y);
    }
}

// ==========================================================================
extern "C" void kernel_launch(void* const* d_in, const int* in_sizes, int n_in,
                              void* d_out, int out_size)
{
    const float* Q  = (const float*)d_in[0];
    const float* K  = (const float*)d_in[1];
    const float* V  = (const float*)d_in[2];
    const float* WQ = (const float*)d_in[3];
    const float* WK = (const float*)d_in[4];
    const float* WV = (const float*)d_in[5];
    const float* WO = (const float*)d_in[6];
    float* out = (float*)d_out;

    pack_w_kernel<<<(3 * D_ * NW) / 256, 256>>>(WQ, WK, WV);
    proj_mma_kernel<<<dim3(128, 3), 128>>>(Q, K, V);
    attn_kernel<<<dim3(B_ * H_, 4), 128>>>();
    outproj_kernel<<<dim3((B_ * S_) / 64, D_ / 128), 256>>>(WO, out);
}

// round 10
// speedup vs baseline: 1.5734x; 1.5734x over previous
#include <cuda_runtime.h>
#include <cuda_bf16.h>
#include <cstdint>

#define B_  4
#define S_  2048
#define D_  1024
#define H_  16
#define DK_ 10
#define DV_ 12
#define HK  (H_*DV_)      // 192
#define PAD 16            // padded row width for q/k/v scratch
#define NW  192           // packed N per section

typedef unsigned long long ull;

// ---------------- scratch (device globals; no allocation allowed) ----------
__device__ __nv_bfloat16 g_wbh[3*D_*NW];    // [sec][d][n] bf16 hi (QKV proj W)
__device__ __nv_bfloat16 g_wbl[3*D_*NW];    // [sec][d][n] bf16 lo
__device__ __nv_bfloat16 g_wobh[HK*D_];     // [k][n] bf16 hi (WO)
__device__ __nv_bfloat16 g_wobl[HK*D_];     // [k][n] bf16 lo
__device__ float g_q[B_*H_*S_*PAD];         // [bh][s][16] (10 valid)
__device__ float g_k[B_*H_*S_*PAD];         // [bh][s][16] (10 valid)
__device__ float g_v[B_*H_*S_*PAD];         // [bh][s][16] (12 valid)
__device__ float g_heads[B_*S_*HK];         // [b*s][192]

// ---------------- packed f32x2 helpers ------------------------------------
__device__ __forceinline__ ull pk2(float lo, float hi) {
    ull r; asm("mov.b64 %0, {%1,%2};" : "=l"(r) : "f"(lo), "f"(hi)); return r;
}
__device__ __forceinline__ ull fma2(ull a, ull b, ull c) {
    ull d; asm("fma.rn.f32x2 %0, %1, %2, %3;" : "=l"(d) : "l"(a), "l"(b), "l"(c)); return d;
}
__device__ __forceinline__ ull mul2(ull a, ull b) {
    ull d; asm("mul.rn.f32x2 %0, %1, %2;" : "=l"(d) : "l"(a), "l"(b)); return d;
}
__device__ __forceinline__ float2 upk2(ull v) {
    float2 r; asm("mov.b64 {%0,%1}, %2;" : "=f"(r.x), "=f"(r.y) : "l"(v)); return r;
}
__device__ __forceinline__ float ex2(float x) {
    float r; asm("ex2.approx.f32 %0, %1;" : "=f"(r) : "f"(x)); return r;
}

// ---------------- legacy tensor helpers (baseline PTX, sm_80-era) ---------
__device__ __forceinline__ uint32_t smem_u32(const void* p) {
    uint32_t a;
    asm("{ .reg .u64 t; cvta.to.shared.u64 t, %1; cvt.u32.u64 %0, t; }" : "=r"(a) : "l"(p));
    return a;
}
__device__ __forceinline__ void ldmx4(uint32_t* r, uint32_t a) {
    asm volatile("ldmatrix.sync.aligned.m8n8.x4.shared.b16 {%0,%1,%2,%3}, [%4];"
                 : "=r"(r[0]), "=r"(r[1]), "=r"(r[2]), "=r"(r[3]) : "r"(a));
}
__device__ __forceinline__ void ldmx4t(uint32_t* r, uint32_t a) {
    asm volatile("ldmatrix.sync.aligned.m8n8.x4.trans.shared.b16 {%0,%1,%2,%3}, [%4];"
                 : "=r"(r[0]), "=r"(r[1]), "=r"(r[2]), "=r"(r[3]) : "r"(a));
}
__device__ __forceinline__ void mma16816(float* c, const uint32_t* a,
                                         uint32_t b0, uint32_t b1) {
    asm volatile(
        "mma.sync.aligned.m16n8k16.row.col.f32.bf16.bf16.f32 "
        "{%0,%1,%2,%3}, {%4,%5,%6,%7}, {%8,%9}, {%0,%1,%2,%3};"
        : "+f"(c[0]), "+f"(c[1]), "+f"(c[2]), "+f"(c[3])
        : "r"(a[0]), "r"(a[1]), "r"(a[2]), "r"(a[3]), "r"(b0), "r"(b1));
}
__device__ __forceinline__ uint32_t bf2u(__nv_bfloat162 v) {
    return *reinterpret_cast<uint32_t*>(&v);
}

// ==========================================================================
// Kernel 0a: pack QKV weights -> bf16 hi/lo, [sec][d][n], n = h*12+j.
// ==========================================================================
__global__ void pack_w_kernel(const float* __restrict__ WQ,
                              const float* __restrict__ WK,
                              const float* __restrict__ WV)
{
    int idx = blockIdx.x * 256 + threadIdx.x;   // 0 .. 3*1024*192-1
    int sec = idx / (D_ * NW);
    int rem = idx - sec * (D_ * NW);
    int d   = rem / NW;
    int n   = rem - d * NW;
    int h   = n / 12, j = n - h * 12;
    float v = 0.f;
    if (sec == 0)      { if (j < DK_) v = WQ[(h * D_ + d) * DK_ + j]; }
    else if (sec == 1) { if (j < DK_) v = WK[(h * D_ + d) * DK_ + j]; }
    else               {              v = WV[(h * D_ + d) * DV_ + j]; }
    __nv_bfloat16 hi = __float2bfloat16(v);
    __nv_bfloat16 lo = __float2bfloat16(v - __bfloat162float(hi));
    g_wbh[idx] = hi;
    g_wbl[idx] = lo;
}

// ==========================================================================
// Kernel 0b: pack WO[192,1024] -> bf16 hi/lo (row-major, as stored).
// ==========================================================================
__global__ void pack_wo_kernel(const float* __restrict__ WO)
{
    int idx = blockIdx.x * 256 + threadIdx.x;   // 0 .. 192*1024-1
    float v = WO[idx];
    __nv_bfloat16 hi = __float2bfloat16(v);
    __nv_bfloat16 lo = __float2bfloat16(v - __bfloat162float(hi));
    g_wobh[idx] = hi;
    g_wobl[idx] = lo;
}

// ==========================================================================
// Kernel 1: projection GEMM on legacy tensor cores (mma.sync bf16, 2-word
// split: ah*bh + ah*bl + al*bh). C tile 64x192 per CTA, BK=32, 4 warps.
// (R8 configuration, known good.)
// ==========================================================================
__global__ void __launch_bounds__(128, 3)
proj_mma_kernel(const float* __restrict__ Qi,
                const float* __restrict__ Ki,
                const float* __restrict__ Vi)
{
    const int z  = blockIdx.y;
    const float* A = (z == 0) ? Qi : (z == 1) ? Ki : Vi;
    const int m0 = blockIdx.x * 64;
    const int tid  = threadIdx.x;     // 128
    const int w    = tid >> 5;
    const int lane = tid & 31;

    __shared__ __align__(16) __nv_bfloat16 Ah[64][40];   // 80B stride
    __shared__ __align__(16) __nv_bfloat16 Al[64][40];
    __shared__ __align__(16) __nv_bfloat16 Bh[32][200];  // 400B stride
    __shared__ __align__(16) __nv_bfloat16 Bl[32][200];

    const uint32_t AhB = smem_u32(&Ah[0][0]);
    const uint32_t AlB = smem_u32(&Al[0][0]);
    const uint32_t BhB = smem_u32(&Bh[0][0]);
    const uint32_t BlB = smem_u32(&Bl[0][0]);

    float acc[24][4];
    #pragma unroll
    for (int t = 0; t < 24; t++)
        #pragma unroll
        for (int u = 0; u < 4; u++) acc[t][u] = 0.f;

    const __nv_bfloat16* wbh = g_wbh + (size_t)z * D_ * NW;
    const __nv_bfloat16* wbl = g_wbl + (size_t)z * D_ * NW;

    for (int k0 = 0; k0 < D_; k0 += 32) {
        #pragma unroll
        for (int l = 0; l < 4; l++) {
            int f   = tid + l * 128;
            int row = f >> 3, c4 = f & 7;
            float4 a = *(const float4*)(A + (size_t)(m0 + row) * D_ + k0 + c4 * 4);
            __nv_bfloat16 hx = __float2bfloat16(a.x), hy = __float2bfloat16(a.y);
            __nv_bfloat16 hz = __float2bfloat16(a.z), hw = __float2bfloat16(a.w);
            __nv_bfloat16 lx = __float2bfloat16(a.x - __bfloat162float(hx));
            __nv_bfloat16 ly = __float2bfloat16(a.y - __bfloat162float(hy));
            __nv_bfloat16 lz = __float2bfloat16(a.z - __bfloat162float(hz));
            __nv_bfloat16 lw = __float2bfloat16(a.w - __bfloat162float(hw));
            *(uint32_t*)&Ah[row][c4 * 4 + 0] = bf2u(__nv_bfloat162(hx, hy));
            *(uint32_t*)&Ah[row][c4 * 4 + 2] = bf2u(__nv_bfloat162(hz, hw));
            *(uint32_t*)&Al[row][c4 * 4 + 0] = bf2u(__nv_bfloat162(lx, ly));
            *(uint32_t*)&Al[row][c4 * 4 + 2] = bf2u(__nv_bfloat162(lz, lw));
        }
        #pragma unroll
        for (int l = 0; l < 6; l++) {
            int idx = tid + l * 128;        // 0..767
            int kk  = idx / 24;
            int u   = idx - kk * 24;
            *(uint4*)&Bh[kk][u * 8] = *(const uint4*)(wbh + (size_t)(k0 + kk) * NW + u * 8);
            *(uint4*)&Bl[kk][u * 8] = *(const uint4*)(wbl + (size_t)(k0 + kk) * NW + u * 8);
        }
        __syncthreads();

        #pragma unroll
        for (int ks = 0; ks < 2; ks++) {
            uint32_t aoff = (uint32_t)(w * 16 + (lane & 15)) * 80
                          + (uint32_t)(ks * 16 + (lane >> 4) * 8) * 2;
            uint32_t ah[4], al[4];
            ldmx4(ah, AhB + aoff);
            ldmx4(al, AlB + aoff);

            uint32_t brow = (uint32_t)(ks * 16 + ((lane >> 3) & 1) * 8 + (lane & 7));
            uint32_t bbase = brow * 400 + (uint32_t)(lane >> 4) * 16;

            #pragma unroll
            for (int nt = 0; nt < 12; nt++) {
                uint32_t bh[4], bl[4];
                ldmx4t(bh, BhB + bbase + nt * 32);
                ldmx4t(bl, BlB + bbase + nt * 32);
                mma16816(acc[nt * 2 + 0], ah, bh[0], bh[1]);
                mma16816(acc[nt * 2 + 0], al, bh[0], bh[1]);
                mma16816(acc[nt * 2 + 0], ah, bl[0], bl[1]);
                mma16816(acc[nt * 2 + 1], ah, bh[2], bh[3]);
                mma16816(acc[nt * 2 + 1], al, bh[2], bh[3]);
                mma16816(acc[nt * 2 + 1], ah, bl[2], bl[3]);
            }
        }
        __syncthreads();
    }

    // ---- epilogue: frag (c0,c1)@row r, (c2,c3)@row r+8; scatter padded ----
    const int b  = m0 >> 11;
    const int s0 = (m0 & 2047) + w * 16 + (lane >> 2);
    const int lc = lane & 3;
    float* base = (z == 0) ? g_q : (z == 1) ? g_k : g_v;
    #pragma unroll
    for (int t = 0; t < 24; t++) {
        int n = t * 8 + lc * 2;          // even -> (n, n+1) same head
        int h = n / 12, j = n - h * 12;
        float* o = base + ((size_t)(b * H_ + h) * S_ + s0) * PAD + j;
        *(float2*)o             = make_float2(acc[t][0], acc[t][1]);
        *(float2*)(o + 8 * PAD) = make_float2(acc[t][2], acc[t][3]);
    }
}

// ==========================================================================
// Kernel 2: streaming attention (R8 configuration, known good).
// ==========================================================================
#define TK 128

__global__ void attn_kernel()
{
    const int bh  = blockIdx.x;
    const int b   = bh >> 4;
    const int h   = bh & 15;
    const int q0  = blockIdx.y * 256;
    const int tid = threadIdx.x;

    const float scale2 = 0.45622024f;   // (1/sqrt(10)) * log2(e)

    ull qa[5], qb[5];
    {
        const float* pa = g_q + ((size_t)bh * S_ + q0 + tid) * PAD;
        const float* pb = pa + (size_t)128 * PAD;
        #pragma unroll
        for (int u = 0; u < 5; u++) {
            qa[u] = pk2(pa[2 * u] * scale2, pa[2 * u + 1] * scale2);
            qb[u] = pk2(pb[2 * u] * scale2, pb[2 * u + 1] * scale2);
        }
    }

    __shared__ __align__(16) float Ks[TK][PAD];
    __shared__ __align__(16) float Vs[TK][PAD];

    ull acca[6] = {0,0,0,0,0,0};
    ull accb[6] = {0,0,0,0,0,0};
    float dena = 0.f, denb = 0.f;

    const float* kbase = g_k + (size_t)bh * S_ * PAD;
    const float* vbase = g_v + (size_t)bh * S_ * PAD;

    for (int t0 = 0; t0 < S_; t0 += TK) {
        {
            const float4* kr = (const float4*)(kbase + (size_t)(t0 + tid) * PAD);
            float4* kd = (float4*)&Ks[tid][0];
            kd[0] = kr[0]; kd[1] = kr[1]; kd[2] = kr[2];
            const float4* vr = (const float4*)(vbase + (size_t)(t0 + tid) * PAD);
            float4* vd = (float4*)&Vs[tid][0];
            vd[0] = vr[0]; vd[1] = vr[1]; vd[2] = vr[2];
        }
        __syncthreads();

        #pragma unroll 4
        for (int j = 0; j < TK; j++) {
            ulonglong2 k01 = *(const ulonglong2*)&Ks[j][0];
            ulonglong2 k23 = *(const ulonglong2*)&Ks[j][4];
            ull        k4  = *(const ull*)&Ks[j][8];

            ull sa2 = mul2(qa[0], k01.x);
            ull sb2 = mul2(qb[0], k01.x);
            sa2 = fma2(qa[1], k01.y, sa2);  sb2 = fma2(qb[1], k01.y, sb2);
            sa2 = fma2(qa[2], k23.x, sa2);  sb2 = fma2(qb[2], k23.x, sb2);
            sa2 = fma2(qa[3], k23.y, sa2);  sb2 = fma2(qb[3], k23.y, sb2);
            sa2 = fma2(qa[4], k4,   sa2);   sb2 = fma2(qb[4], k4,   sb2);
            float2 fa = upk2(sa2), fb = upk2(sb2);
            float pa = ex2(fa.x + fa.y);
            float pb = ex2(fb.x + fb.y);
            dena += pa; denb += pb;
            ull ppa = pk2(pa, pa), ppb = pk2(pb, pb);

            ulonglong2 v01 = *(const ulonglong2*)&Vs[j][0];
            ulonglong2 v23 = *(const ulonglong2*)&Vs[j][4];
            ulonglong2 v45 = *(const ulonglong2*)&Vs[j][8];
            acca[0] = fma2(ppa, v01.x, acca[0]);  accb[0] = fma2(ppb, v01.x, accb[0]);
            acca[1] = fma2(ppa, v01.y, acca[1]);  accb[1] = fma2(ppb, v01.y, accb[1]);
            acca[2] = fma2(ppa, v23.x, acca[2]);  accb[2] = fma2(ppb, v23.x, accb[2]);
            acca[3] = fma2(ppa, v23.y, acca[3]);  accb[3] = fma2(ppb, v23.y, accb[3]);
            acca[4] = fma2(ppa, v45.x, acca[4]);  accb[4] = fma2(ppb, v45.x, accb[4]);
            acca[5] = fma2(ppa, v45.y, acca[5]);  accb[5] = fma2(ppb, v45.y, accb[5]);
        }
        __syncthreads();
    }

    const float inva = 1.f / dena;
    const float invb = 1.f / denb;
    float* oa = g_heads + ((size_t)(b * S_ + q0 + tid)) * HK + h * DV_;
    float* ob = oa + (size_t)128 * HK;
    {
        float2 r0 = upk2(acca[0]), r1 = upk2(acca[1]), r2 = upk2(acca[2]);
        float2 r3 = upk2(acca[3]), r4 = upk2(acca[4]), r5 = upk2(acca[5]);
        *(float4*)(oa + 0) = make_float4(r0.x * inva, r0.y * inva, r1.x * inva, r1.y * inva);
        *(float4*)(oa + 4) = make_float4(r2.x * inva, r2.y * inva, r3.x * inva, r3.y * inva);
        *(float4*)(oa + 8) = make_float4(r4.x * inva, r4.y * inva, r5.x * inva, r5.y * inva);
    }
    {
        float2 r0 = upk2(accb[0]), r1 = upk2(accb[1]), r2 = upk2(accb[2]);
        float2 r3 = upk2(accb[3]), r4 = upk2(accb[4]), r5 = upk2(accb[5]);
        *(float4*)(ob + 0) = make_float4(r0.x * invb, r0.y * invb, r1.x * invb, r1.y * invb);
        *(float4*)(ob + 4) = make_float4(r2.x * invb, r2.y * invb, r3.x * invb, r3.y * invb);
        *(float4*)(ob + 8) = make_float4(r4.x * invb, r4.y * invb, r5.x * invb, r5.y * invb);
    }
}

// ==========================================================================
// Kernel 3: output projection on legacy tensor cores.
// out[8192,1024] = heads[8192,192] @ WO[192,1024]; bf16 3-term split.
// C tile 64x128 per CTA, BK=32 (6 iters), 4 warps; warp = 16 rows x 128 cols.
// Same staging/ldmatrix pattern as proj_mma (proven).
// ==========================================================================
__global__ void __launch_bounds__(128, 4)
outproj_mma_kernel(float* __restrict__ out)
{
    const int m0 = blockIdx.x * 64;
    const int n0 = blockIdx.y * 128;
    const int tid  = threadIdx.x;     // 128
    const int w    = tid >> 5;
    const int lane = tid & 31;

    __shared__ __align__(16) __nv_bfloat16 Ah[64][40];   // 80B stride
    __shared__ __align__(16) __nv_bfloat16 Al[64][40];
    __shared__ __align__(16) __nv_bfloat16 Bh[32][136];  // 272B stride
    __shared__ __align__(16) __nv_bfloat16 Bl[32][136];

    const uint32_t AhB = smem_u32(&Ah[0][0]);
    const uint32_t AlB = smem_u32(&Al[0][0]);
    const uint32_t BhB = smem_u32(&Bh[0][0]);
    const uint32_t BlB = smem_u32(&Bl[0][0]);

    float acc[16][4];
    #pragma unroll
    for (int t = 0; t < 16; t++)
        #pragma unroll
        for (int u = 0; u < 4; u++) acc[t][u] = 0.f;

    for (int k0 = 0; k0 < HK; k0 += 32) {
        // ---- stage A: 64x32 f32 heads -> bf16 hi/lo. 512 f4, 4/thread ----
        #pragma unroll
        for (int l = 0; l < 4; l++) {
            int f   = tid + l * 128;
            int row = f >> 3, c4 = f & 7;
            float4 a = *(const float4*)(g_heads + (size_t)(m0 + row) * HK + k0 + c4 * 4);
            __nv_bfloat16 hx = __float2bfloat16(a.x), hy = __float2bfloat16(a.y);
            __nv_bfloat16 hz = __float2bfloat16(a.z), hw = __float2bfloat16(a.w);
            __nv_bfloat16 lx = __float2bfloat16(a.x - __bfloat162float(hx));
            __nv_bfloat16 ly = __float2bfloat16(a.y - __bfloat162float(hy));
            __nv_bfloat16 lz = __float2bfloat16(a.z - __bfloat162float(hz));
            __nv_bfloat16 lw = __float2bfloat16(a.w - __bfloat162float(hw));
            *(uint32_t*)&Ah[row][c4 * 4 + 0] = bf2u(__nv_bfloat162(hx, hy));
            *(uint32_t*)&Ah[row][c4 * 4 + 2] = bf2u(__nv_bfloat162(hz, hw));
            *(uint32_t*)&Al[row][c4 * 4 + 0] = bf2u(__nv_bfloat162(lx, ly));
            *(uint32_t*)&Al[row][c4 * 4 + 2] = bf2u(__nv_bfloat162(lz, lw));
        }
        // ---- stage B: 32x128 bf16 hi/lo, uint4 copies, 4+4 per thread ----
        #pragma unroll
        for (int l = 0; l < 4; l++) {
            int idx = tid + l * 128;        // 0..511
            int kk  = idx >> 4;             // 16 uint4 per row
            int u   = idx & 15;
            *(uint4*)&Bh[kk][u * 8] = *(const uint4*)(g_wobh + (size_t)(k0 + kk) * D_ + n0 + u * 8);
            *(uint4*)&Bl[kk][u * 8] = *(const uint4*)(g_wobl + (size_t)(k0 + kk) * D_ + n0 + u * 8);
        }
        __syncthreads();

        #pragma unroll
        for (int ks = 0; ks < 2; ks++) {
            uint32_t aoff = (uint32_t)(w * 16 + (lane & 15)) * 80
                          + (uint32_t)(ks * 16 + (lane >> 4) * 8) * 2;
            uint32_t ah[4], al[4];
            ldmx4(ah, AhB + aoff);
            ldmx4(al, AlB + aoff);

            uint32_t brow = (uint32_t)(ks * 16 + ((lane >> 3) & 1) * 8 + (lane & 7));
            uint32_t bbase = brow * 272 + (uint32_t)(lane >> 4) * 16;

            #pragma unroll
            for (int nt = 0; nt < 8; nt++) {
                uint32_t bh[4], bl[4];
                ldmx4t(bh, BhB + bbase + nt * 32);
                ldmx4t(bl, BlB + bbase + nt * 32);
                mma16816(acc[nt * 2 + 0], ah, bh[0], bh[1]);
                mma16816(acc[nt * 2 + 0], al, bh[0], bh[1]);
                mma16816(acc[nt * 2 + 0], ah, bl[0], bl[1]);
                mma16816(acc[nt * 2 + 1], ah, bh[2], bh[3]);
                mma16816(acc[nt * 2 + 1], al, bh[2], bh[3]);
                mma16816(acc[nt * 2 + 1], ah, bl[2], bl[3]);
            }
        }
        __syncthreads();
    }

    // ---- epilogue: frag (c0,c1)@row r, (c2,c3)@row r+8 ----
    const int r0 = m0 + w * 16 + (lane >> 2);
    const int lc = lane & 3;
    #pragma unroll
    for (int t = 0; t < 16; t++) {
        int n = n0 + t * 8 + lc * 2;
        float* o = out + (size_t)r0 * D_ + n;
        *(float2*)o            = make_float2(acc[t][0], acc[t][1]);
        *(float2*)(o + 8 * D_) = make_float2(acc[t][2], acc[t][3]);
    }
}

// ==========================================================================
extern "C" void kernel_launch(void* const* d_in, const int* in_sizes, int n_in,
                              void* d_out, int out_size)
{
    const float* Q  = (const float*)d_in[0];
    const float* K  = (const float*)d_in[1];
    const float* V  = (const float*)d_in[2];
    const float* WQ = (const float*)d_in[3];
    const float* WK = (const float*)d_in[4];
    const float* WV = (const float*)d_in[5];
    const float* WO = (const float*)d_in[6];
    float* out = (float*)d_out;

    pack_w_kernel<<<(3 * D_ * NW) / 256, 256>>>(WQ, WK, WV);
    pack_wo_kernel<<<(HK * D_) / 256, 256>>>(WO);
    proj_mma_kernel<<<dim3(128, 3), 128>>>(Q, K, V);
    attn_kernel<<<dim3(B_ * H_, S_ / 256), 128>>>();
    outproj_mma_kernel<<<dim3((B_ * S_) / 64, D_ / 128), 128>>>(out);
}

// round 11
// speedup vs baseline: 1.7899x; 1.1376x over previous
#include <cuda_runtime.h>
#include <cuda_bf16.h>
#include <cstdint>

#define B_  4
#define S_  2048
#define D_  1024
#define H_  16
#define DK_ 10
#define DV_ 12
#define HK  (H_*DV_)      // 192
#define PAD 16            // padded row width for q/k/v scratch
#define NW  192           // packed N per section
#define KSPLIT 2          // key-dimension split for attention

typedef unsigned long long ull;

// ---------------- scratch (device globals; no allocation allowed) ----------
__device__ __nv_bfloat16 g_wbh[3*D_*NW];    // [sec][d][n] bf16 hi (QKV proj W)
__device__ __nv_bfloat16 g_wbl[3*D_*NW];    // [sec][d][n] bf16 lo
__device__ __nv_bfloat16 g_wobh[HK*D_];     // [k][n] bf16 hi (WO)
__device__ __nv_bfloat16 g_wobl[HK*D_];     // [k][n] bf16 lo
__device__ float g_q[B_*H_*S_*PAD];         // [bh][s][16] (10 valid)
__device__ float g_k[B_*H_*S_*PAD];         // [bh][s][16] (10 valid)
__device__ float g_v[B_*H_*S_*PAD];         // [bh][s][16] (12 valid)
__device__ float g_part[KSPLIT*B_*H_*S_*16]; // [g][bh][s][16]: 12 num + den
__device__ float g_heads[B_*S_*HK];         // [b*s][192]

// ---------------- packed f32x2 helpers ------------------------------------
__device__ __forceinline__ ull pk2(float lo, float hi) {
    ull r; asm("mov.b64 %0, {%1,%2};" : "=l"(r) : "f"(lo), "f"(hi)); return r;
}
__device__ __forceinline__ ull fma2(ull a, ull b, ull c) {
    ull d; asm("fma.rn.f32x2 %0, %1, %2, %3;" : "=l"(d) : "l"(a), "l"(b), "l"(c)); return d;
}
__device__ __forceinline__ ull mul2(ull a, ull b) {
    ull d; asm("mul.rn.f32x2 %0, %1, %2;" : "=l"(d) : "l"(a), "l"(b)); return d;
}
__device__ __forceinline__ float2 upk2(ull v) {
    float2 r; asm("mov.b64 {%0,%1}, %2;" : "=f"(r.x), "=f"(r.y) : "l"(v)); return r;
}
__device__ __forceinline__ float ex2(float x) {
    float r; asm("ex2.approx.f32 %0, %1;" : "=f"(r) : "f"(x)); return r;
}

// ---------------- legacy tensor helpers (baseline PTX, sm_80-era) ---------
__device__ __forceinline__ uint32_t smem_u32(const void* p) {
    uint32_t a;
    asm("{ .reg .u64 t; cvta.to.shared.u64 t, %1; cvt.u32.u64 %0, t; }" : "=r"(a) : "l"(p));
    return a;
}
__device__ __forceinline__ void ldmx4(uint32_t* r, uint32_t a) {
    asm volatile("ldmatrix.sync.aligned.m8n8.x4.shared.b16 {%0,%1,%2,%3}, [%4];"
                 : "=r"(r[0]), "=r"(r[1]), "=r"(r[2]), "=r"(r[3]) : "r"(a));
}
__device__ __forceinline__ void ldmx4t(uint32_t* r, uint32_t a) {
    asm volatile("ldmatrix.sync.aligned.m8n8.x4.trans.shared.b16 {%0,%1,%2,%3}, [%4];"
                 : "=r"(r[0]), "=r"(r[1]), "=r"(r[2]), "=r"(r[3]) : "r"(a));
}
__device__ __forceinline__ void mma16816(float* c, const uint32_t* a,
                                         uint32_t b0, uint32_t b1) {
    asm volatile(
        "mma.sync.aligned.m16n8k16.row.col.f32.bf16.bf16.f32 "
        "{%0,%1,%2,%3}, {%4,%5,%6,%7}, {%8,%9}, {%0,%1,%2,%3};"
        : "+f"(c[0]), "+f"(c[1]), "+f"(c[2]), "+f"(c[3])
        : "r"(a[0]), "r"(a[1]), "r"(a[2]), "r"(a[3]), "r"(b0), "r"(b1));
}
__device__ __forceinline__ uint32_t bf2u(__nv_bfloat162 v) {
    return *reinterpret_cast<uint32_t*>(&v);
}

// ==========================================================================
// Kernel 0a: pack QKV weights -> bf16 hi/lo, [sec][d][n], n = h*12+j.
// ==========================================================================
__global__ void pack_w_kernel(const float* __restrict__ WQ,
                              const float* __restrict__ WK,
                              const float* __restrict__ WV)
{
    int idx = blockIdx.x * 256 + threadIdx.x;   // 0 .. 3*1024*192-1
    int sec = idx / (D_ * NW);
    int rem = idx - sec * (D_ * NW);
    int d   = rem / NW;
    int n   = rem - d * NW;
    int h   = n / 12, j = n - h * 12;
    float v = 0.f;
    if (sec == 0)      { if (j < DK_) v = WQ[(h * D_ + d) * DK_ + j]; }
    else if (sec == 1) { if (j < DK_) v = WK[(h * D_ + d) * DK_ + j]; }
    else               {              v = WV[(h * D_ + d) * DV_ + j]; }
    __nv_bfloat16 hi = __float2bfloat16(v);
    __nv_bfloat16 lo = __float2bfloat16(v - __bfloat162float(hi));
    g_wbh[idx] = hi;
    g_wbl[idx] = lo;
}

// ==========================================================================
// Kernel 0b: pack WO[192,1024] -> bf16 hi/lo (row-major, as stored).
// ==========================================================================
__global__ void pack_wo_kernel(const float* __restrict__ WO)
{
    int idx = blockIdx.x * 256 + threadIdx.x;   // 0 .. 192*1024-1
    float v = WO[idx];
    __nv_bfloat16 hi = __float2bfloat16(v);
    __nv_bfloat16 lo = __float2bfloat16(v - __bfloat162float(hi));
    g_wobh[idx] = hi;
    g_wobl[idx] = lo;
}

// ==========================================================================
// Kernel 1: projection GEMM on legacy tensor cores (mma.sync bf16, 2-word
// split: ah*bh + ah*bl + al*bh). C tile 64x192 per CTA, BK=32, 4 warps.
// (R8 configuration, known good.)
// ==========================================================================
__global__ void __launch_bounds__(128, 3)
proj_mma_kernel(const float* __restrict__ Qi,
                const float* __restrict__ Ki,
                const float* __restrict__ Vi)
{
    const int z  = blockIdx.y;
    const float* A = (z == 0) ? Qi : (z == 1) ? Ki : Vi;
    const int m0 = blockIdx.x * 64;
    const int tid  = threadIdx.x;     // 128
    const int w    = tid >> 5;
    const int lane = tid & 31;

    __shared__ __align__(16) __nv_bfloat16 Ah[64][40];   // 80B stride
    __shared__ __align__(16) __nv_bfloat16 Al[64][40];
    __shared__ __align__(16) __nv_bfloat16 Bh[32][200];  // 400B stride
    __shared__ __align__(16) __nv_bfloat16 Bl[32][200];

    const uint32_t AhB = smem_u32(&Ah[0][0]);
    const uint32_t AlB = smem_u32(&Al[0][0]);
    const uint32_t BhB = smem_u32(&Bh[0][0]);
    const uint32_t BlB = smem_u32(&Bl[0][0]);

    float acc[24][4];
    #pragma unroll
    for (int t = 0; t < 24; t++)
        #pragma unroll
        for (int u = 0; u < 4; u++) acc[t][u] = 0.f;

    const __nv_bfloat16* wbh = g_wbh + (size_t)z * D_ * NW;
    const __nv_bfloat16* wbl = g_wbl + (size_t)z * D_ * NW;

    for (int k0 = 0; k0 < D_; k0 += 32) {
        #pragma unroll
        for (int l = 0; l < 4; l++) {
            int f   = tid + l * 128;
            int row = f >> 3, c4 = f & 7;
            float4 a = *(const float4*)(A + (size_t)(m0 + row) * D_ + k0 + c4 * 4);
            __nv_bfloat16 hx = __float2bfloat16(a.x), hy = __float2bfloat16(a.y);
            __nv_bfloat16 hz = __float2bfloat16(a.z), hw = __float2bfloat16(a.w);
            __nv_bfloat16 lx = __float2bfloat16(a.x - __bfloat162float(hx));
            __nv_bfloat16 ly = __float2bfloat16(a.y - __bfloat162float(hy));
            __nv_bfloat16 lz = __float2bfloat16(a.z - __bfloat162float(hz));
            __nv_bfloat16 lw = __float2bfloat16(a.w - __bfloat162float(hw));
            *(uint32_t*)&Ah[row][c4 * 4 + 0] = bf2u(__nv_bfloat162(hx, hy));
            *(uint32_t*)&Ah[row][c4 * 4 + 2] = bf2u(__nv_bfloat162(hz, hw));
            *(uint32_t*)&Al[row][c4 * 4 + 0] = bf2u(__nv_bfloat162(lx, ly));
            *(uint32_t*)&Al[row][c4 * 4 + 2] = bf2u(__nv_bfloat162(lz, lw));
        }
        #pragma unroll
        for (int l = 0; l < 6; l++) {
            int idx = tid + l * 128;        // 0..767
            int kk  = idx / 24;
            int u   = idx - kk * 24;
            *(uint4*)&Bh[kk][u * 8] = *(const uint4*)(wbh + (size_t)(k0 + kk) * NW + u * 8);
            *(uint4*)&Bl[kk][u * 8] = *(const uint4*)(wbl + (size_t)(k0 + kk) * NW + u * 8);
        }
        __syncthreads();

        #pragma unroll
        for (int ks = 0; ks < 2; ks++) {
            uint32_t aoff = (uint32_t)(w * 16 + (lane & 15)) * 80
                          + (uint32_t)(ks * 16 + (lane >> 4) * 8) * 2;
            uint32_t ah[4], al[4];
            ldmx4(ah, AhB + aoff);
            ldmx4(al, AlB + aoff);

            uint32_t brow = (uint32_t)(ks * 16 + ((lane >> 3) & 1) * 8 + (lane & 7));
            uint32_t bbase = brow * 400 + (uint32_t)(lane >> 4) * 16;

            #pragma unroll
            for (int nt = 0; nt < 12; nt++) {
                uint32_t bh[4], bl[4];
                ldmx4t(bh, BhB + bbase + nt * 32);
                ldmx4t(bl, BlB + bbase + nt * 32);
                mma16816(acc[nt * 2 + 0], ah, bh[0], bh[1]);
                mma16816(acc[nt * 2 + 0], al, bh[0], bh[1]);
                mma16816(acc[nt * 2 + 0], ah, bl[0], bl[1]);
                mma16816(acc[nt * 2 + 1], ah, bh[2], bh[3]);
                mma16816(acc[nt * 2 + 1], al, bh[2], bh[3]);
                mma16816(acc[nt * 2 + 1], ah, bl[2], bl[3]);
            }
        }
        __syncthreads();
    }

    // ---- epilogue: frag (c0,c1)@row r, (c2,c3)@row r+8; scatter padded ----
    const int b  = m0 >> 11;
    const int s0 = (m0 & 2047) + w * 16 + (lane >> 2);
    const int lc = lane & 3;
    float* base = (z == 0) ? g_q : (z == 1) ? g_k : g_v;
    #pragma unroll
    for (int t = 0; t < 24; t++) {
        int n = t * 8 + lc * 2;          // even -> (n, n+1) same head
        int h = n / 12, j = n - h * 12;
        float* o = base + ((size_t)(b * H_ + h) * S_ + s0) * PAD + j;
        *(float2*)o             = make_float2(acc[t][0], acc[t][1]);
        *(float2*)(o + 8 * PAD) = make_float2(acc[t][2], acc[t][3]);
    }
}

// ==========================================================================
// Kernel 2: streaming attention, key-split for occupancy.
// grid (64 bh, 8 q-tiles, KSPLIT key-halves); 128 thr, 2 queries/thread.
// Max-free softmax is LINEAR in keys: partial (sum p*v, sum p) just add.
// Each CTA writes 13 partial floats per (query,head) to g_part[z].
// ==========================================================================
#define TK 128

__global__ void __launch_bounds__(128, 6) attn_kernel()
{
    const int bh  = blockIdx.x;
    const int q0  = blockIdx.y * 256;
    const int z   = blockIdx.z;        // key half
    const int tid = threadIdx.x;

    const float scale2 = 0.45622024f;   // (1/sqrt(10)) * log2(e)

    ull qa[5], qb[5];
    {
        const float* pa = g_q + ((size_t)bh * S_ + q0 + tid) * PAD;
        const float* pb = pa + (size_t)128 * PAD;
        #pragma unroll
        for (int u = 0; u < 5; u++) {
            qa[u] = pk2(pa[2 * u] * scale2, pa[2 * u + 1] * scale2);
            qb[u] = pk2(pb[2 * u] * scale2, pb[2 * u + 1] * scale2);
        }
    }

    __shared__ __align__(16) float Ks[TK][PAD];
    __shared__ __align__(16) float Vs[TK][PAD];

    ull acca[6] = {0,0,0,0,0,0};
    ull accb[6] = {0,0,0,0,0,0};
    float dena = 0.f, denb = 0.f;

    const float* kbase = g_k + (size_t)bh * S_ * PAD;
    const float* vbase = g_v + (size_t)bh * S_ * PAD;
    const int t_lo = z * (S_ / KSPLIT);
    const int t_hi = t_lo + S_ / KSPLIT;

    for (int t0 = t_lo; t0 < t_hi; t0 += TK) {
        {
            const float4* kr = (const float4*)(kbase + (size_t)(t0 + tid) * PAD);
            float4* kd = (float4*)&Ks[tid][0];
            kd[0] = kr[0]; kd[1] = kr[1]; kd[2] = kr[2];
            const float4* vr = (const float4*)(vbase + (size_t)(t0 + tid) * PAD);
            float4* vd = (float4*)&Vs[tid][0];
            vd[0] = vr[0]; vd[1] = vr[1]; vd[2] = vr[2];
        }
        __syncthreads();

        #pragma unroll 4
        for (int j = 0; j < TK; j++) {
            ulonglong2 k01 = *(const ulonglong2*)&Ks[j][0];
            ulonglong2 k23 = *(const ulonglong2*)&Ks[j][4];
            ull        k4  = *(const ull*)&Ks[j][8];

            ull sa2 = mul2(qa[0], k01.x);
            ull sb2 = mul2(qb[0], k01.x);
            sa2 = fma2(qa[1], k01.y, sa2);  sb2 = fma2(qb[1], k01.y, sb2);
            sa2 = fma2(qa[2], k23.x, sa2);  sb2 = fma2(qb[2], k23.x, sb2);
            sa2 = fma2(qa[3], k23.y, sa2);  sb2 = fma2(qb[3], k23.y, sb2);
            sa2 = fma2(qa[4], k4,   sa2);   sb2 = fma2(qb[4], k4,   sb2);
            float2 fa = upk2(sa2), fb = upk2(sb2);
            float pa = ex2(fa.x + fa.y);
            float pb = ex2(fb.x + fb.y);
            dena += pa; denb += pb;
            ull ppa = pk2(pa, pa), ppb = pk2(pb, pb);

            ulonglong2 v01 = *(const ulonglong2*)&Vs[j][0];
            ulonglong2 v23 = *(const ulonglong2*)&Vs[j][4];
            ulonglong2 v45 = *(const ulonglong2*)&Vs[j][8];
            acca[0] = fma2(ppa, v01.x, acca[0]);  accb[0] = fma2(ppb, v01.x, accb[0]);
            acca[1] = fma2(ppa, v01.y, acca[1]);  accb[1] = fma2(ppb, v01.y, accb[1]);
            acca[2] = fma2(ppa, v23.x, acca[2]);  accb[2] = fma2(ppb, v23.x, accb[2]);
            acca[3] = fma2(ppa, v23.y, acca[3]);  accb[3] = fma2(ppb, v23.y, accb[3]);
            acca[4] = fma2(ppa, v45.x, acca[4]);  accb[4] = fma2(ppb, v45.x, accb[4]);
            acca[5] = fma2(ppa, v45.y, acca[5]);  accb[5] = fma2(ppb, v45.y, accb[5]);
        }
        __syncthreads();
    }

    // write partials: [z][bh][s][16] = 12 num + den (+3 pad)
    float* oa = g_part + (((size_t)z * (B_ * H_) + bh) * S_ + (q0 + tid)) * 16;
    float* ob = oa + (size_t)128 * 16;
    {
        float2 r0 = upk2(acca[0]), r1 = upk2(acca[1]), r2 = upk2(acca[2]);
        float2 r3 = upk2(acca[3]), r4 = upk2(acca[4]), r5 = upk2(acca[5]);
        *(float4*)(oa + 0)  = make_float4(r0.x, r0.y, r1.x, r1.y);
        *(float4*)(oa + 4)  = make_float4(r2.x, r2.y, r3.x, r3.y);
        *(float4*)(oa + 8)  = make_float4(r4.x, r4.y, r5.x, r5.y);
        *(float4*)(oa + 12) = make_float4(dena, 0.f, 0.f, 0.f);
    }
    {
        float2 r0 = upk2(accb[0]), r1 = upk2(accb[1]), r2 = upk2(accb[2]);
        float2 r3 = upk2(accb[3]), r4 = upk2(accb[4]), r5 = upk2(accb[5]);
        *(float4*)(ob + 0)  = make_float4(r0.x, r0.y, r1.x, r1.y);
        *(float4*)(ob + 4)  = make_float4(r2.x, r2.y, r3.x, r3.y);
        *(float4*)(ob + 8)  = make_float4(r4.x, r4.y, r5.x, r5.y);
        *(float4*)(ob + 12) = make_float4(denb, 0.f, 0.f, 0.f);
    }
}

// ==========================================================================
// Kernel 2b: reduce key-split partials -> g_heads (divide by total den).
// One thread per (bh, s) row.
// ==========================================================================
__global__ void attn_reduce_kernel()
{
    int idx = blockIdx.x * 256 + threadIdx.x;   // 0 .. 64*2048-1
    int bh = idx >> 11;
    int s  = idx & 2047;
    int b  = bh >> 4, h = bh & 15;

    const float* r0 = g_part + ((size_t)bh * S_ + s) * 16;
    const float* r1 = r0 + (size_t)(B_ * H_) * S_ * 16;

    float4 a0 = *(const float4*)(r0 + 0),  b0 = *(const float4*)(r1 + 0);
    float4 a1 = *(const float4*)(r0 + 4),  b1 = *(const float4*)(r1 + 4);
    float4 a2 = *(const float4*)(r0 + 8),  b2 = *(const float4*)(r1 + 8);
    float  da = r0[12], db = r1[12];

    float inv = 1.f / (da + db);
    float* o = g_heads + ((size_t)(b * S_ + s)) * HK + h * DV_;
    *(float4*)(o + 0) = make_float4((a0.x + b0.x) * inv, (a0.y + b0.y) * inv,
                                    (a0.z + b0.z) * inv, (a0.w + b0.w) * inv);
    *(float4*)(o + 4) = make_float4((a1.x + b1.x) * inv, (a1.y + b1.y) * inv,
                                    (a1.z + b1.z) * inv, (a1.w + b1.w) * inv);
    *(float4*)(o + 8) = make_float4((a2.x + b2.x) * inv, (a2.y + b2.y) * inv,
                                    (a2.z + b2.z) * inv, (a2.w + b2.w) * inv);
}

// ==========================================================================
// Kernel 3: output projection on legacy tensor cores (R10 config).
// ==========================================================================
__global__ void __launch_bounds__(128, 4)
outproj_mma_kernel(float* __restrict__ out)
{
    const int m0 = blockIdx.x * 64;
    const int n0 = blockIdx.y * 128;
    const int tid  = threadIdx.x;     // 128
    const int w    = tid >> 5;
    const int lane = tid & 31;

    __shared__ __align__(16) __nv_bfloat16 Ah[64][40];   // 80B stride
    __shared__ __align__(16) __nv_bfloat16 Al[64][40];
    __shared__ __align__(16) __nv_bfloat16 Bh[32][136];  // 272B stride
    __shared__ __align__(16) __nv_bfloat16 Bl[32][136];

    const uint32_t AhB = smem_u32(&Ah[0][0]);
    const uint32_t AlB = smem_u32(&Al[0][0]);
    const uint32_t BhB = smem_u32(&Bh[0][0]);
    const uint32_t BlB = smem_u32(&Bl[0][0]);

    float acc[16][4];
    #pragma unroll
    for (int t = 0; t < 16; t++)
        #pragma unroll
        for (int u = 0; u < 4; u++) acc[t][u] = 0.f;

    for (int k0 = 0; k0 < HK; k0 += 32) {
        #pragma unroll
        for (int l = 0; l < 4; l++) {
            int f   = tid + l * 128;
            int row = f >> 3, c4 = f & 7;
            float4 a = *(const float4*)(g_heads + (size_t)(m0 + row) * HK + k0 + c4 * 4);
            __nv_bfloat16 hx = __float2bfloat16(a.x), hy = __float2bfloat16(a.y);
            __nv_bfloat16 hz = __float2bfloat16(a.z), hw = __float2bfloat16(a.w);
            __nv_bfloat16 lx = __float2bfloat16(a.x - __bfloat162float(hx));
            __nv_bfloat16 ly = __float2bfloat16(a.y - __bfloat162float(hy));
            __nv_bfloat16 lz = __float2bfloat16(a.z - __bfloat162float(hz));
            __nv_bfloat16 lw = __float2bfloat16(a.w - __bfloat162float(hw));
            *(uint32_t*)&Ah[row][c4 * 4 + 0] = bf2u(__nv_bfloat162(hx, hy));
            *(uint32_t*)&Ah[row][c4 * 4 + 2] = bf2u(__nv_bfloat162(hz, hw));
            *(uint32_t*)&Al[row][c4 * 4 + 0] = bf2u(__nv_bfloat162(lx, ly));
            *(uint32_t*)&Al[row][c4 * 4 + 2] = bf2u(__nv_bfloat162(lz, lw));
        }
        #pragma unroll
        for (int l = 0; l < 4; l++) {
            int idx = tid + l * 128;        // 0..511
            int kk  = idx >> 4;             // 16 uint4 per row
            int u   = idx & 15;
            *(uint4*)&Bh[kk][u * 8] = *(const uint4*)(g_wobh + (size_t)(k0 + kk) * D_ + n0 + u * 8);
            *(uint4*)&Bl[kk][u * 8] = *(const uint4*)(g_wobl + (size_t)(k0 + kk) * D_ + n0 + u * 8);
        }
        __syncthreads();

        #pragma unroll
        for (int ks = 0; ks < 2; ks++) {
            uint32_t aoff = (uint32_t)(w * 16 + (lane & 15)) * 80
                          + (uint32_t)(ks * 16 + (lane >> 4) * 8) * 2;
            uint32_t ah[4], al[4];
            ldmx4(ah, AhB + aoff);
            ldmx4(al, AlB + aoff);

            uint32_t brow = (uint32_t)(ks * 16 + ((lane >> 3) & 1) * 8 + (lane & 7));
            uint32_t bbase = brow * 272 + (uint32_t)(lane >> 4) * 16;

            #pragma unroll
            for (int nt = 0; nt < 8; nt++) {
                uint32_t bh[4], bl[4];
                ldmx4t(bh, BhB + bbase + nt * 32);
                ldmx4t(bl, BlB + bbase + nt * 32);
                mma16816(acc[nt * 2 + 0], ah, bh[0], bh[1]);
                mma16816(acc[nt * 2 + 0], al, bh[0], bh[1]);
                mma16816(acc[nt * 2 + 0], ah, bl[0], bl[1]);
                mma16816(acc[nt * 2 + 1], ah, bh[2], bh[3]);
                mma16816(acc[nt * 2 + 1], al, bh[2], bh[3]);
                mma16816(acc[nt * 2 + 1], ah, bl[2], bl[3]);
            }
        }
        __syncthreads();
    }

    const int r0 = m0 + w * 16 + (lane >> 2);
    const int lc = lane & 3;
    #pragma unroll
    for (int t = 0; t < 16; t++) {
        int n = n0 + t * 8 + lc * 2;
        float* o = out + (size_t)r0 * D_ + n;
        *(float2*)o            = make_float2(acc[t][0], acc[t][1]);
        *(float2*)(o + 8 * D_) = make_float2(acc[t][2], acc[t][3]);
    }
}

// ==========================================================================
extern "C" void kernel_launch(void* const* d_in, const int* in_sizes, int n_in,
                              void* d_out, int out_size)
{
    const float* Q  = (const float*)d_in[0];
    const float* K  = (const float*)d_in[1];
    const float* V  = (const float*)d_in[2];
    const float* WQ = (const float*)d_in[3];
    const float* WK = (const float*)d_in[4];
    const float* WV = (const float*)d_in[5];
    const float* WO = (const float*)d_in[6];
    float* out = (float*)d_out;

    pack_w_kernel<<<(3 * D_ * NW) / 256, 256>>>(WQ, WK, WV);
    pack_wo_kernel<<<(HK * D_) / 256, 256>>>(WO);
    proj_mma_kernel<<<dim3(128, 3), 128>>>(Q, K, V);
    attn_kernel<<<dim3(B_ * H_, S_ / 256, KSPLIT), 128>>>();
    attn_reduce_kernel<<<(B_ * H_ * S_) / 256, 256>>>();
    outproj_mma_kernel<<<dim3((B_ * S_) / 64, D_ / 128), 128>>>(out);
}